// round 11
// baseline (speedup 1.0000x reference)
#include <cuda_runtime.h>
#include <cuda_bf16.h>
#include <cuda_fp16.h>

// Problem constants
#define B_   16
#define TE_  128
#define TD_  128
#define H_   256

#define BM 128
#define BN 64
#define BK 16

// Scratch (device globals)
__device__ float g_ortho[B_ * TE_ * H_];   // enc - cumsum_excl(enc)
__device__ float g_was  [B_ * TE_ * H_];   // scanned enc@Wa
__device__ float g_uah  [B_ * TD_ * H_];   // dec @ U_a

__device__ __forceinline__ __half2 tanh2_fast(__half2 x) {
    unsigned xi = *(unsigned*)&x, yi;
    asm("tanh.approx.f16x2 %0, %1;" : "=r"(yi) : "r"(xi));
    return *(__half2*)&yi;
}

// ---------------------------------------------------------------------------
// Scan block: out[b, t, hg*32+hl] = in[b,t,..] - sum_{t'<t} in[b,t',..]
// ---------------------------------------------------------------------------
__device__ __forceinline__ void scan_block(const float* __restrict__ in,
                                           float* __restrict__ out,
                                           int b, int hg, float* sm /*>=128*33*/) {
    const int tid  = threadIdx.x;
    const int warp = tid >> 5;
    const int lane = tid & 31;

    const float* base = in + (b * TE_) * H_ + hg * 32;
#pragma unroll
    for (int k = 0; k < 16; k++) {
        int idx = tid + k * 256;
        int t = idx >> 5, hl = idx & 31;
        sm[t * 33 + hl] = base[t * H_ + hl];
    }
    __syncthreads();

#pragma unroll
    for (int c = 0; c < 4; c++) {
        int h = warp * 4 + c;
        float a0 = sm[(4 * lane + 0) * 33 + h];
        float a1 = sm[(4 * lane + 1) * 33 + h];
        float a2 = sm[(4 * lane + 2) * 33 + h];
        float a3 = sm[(4 * lane + 3) * 33 + h];
        float L = (a0 + a1) + (a2 + a3);
        float sc = L;
#pragma unroll
        for (int o = 1; o < 32; o <<= 1) {
            float v = __shfl_up_sync(0xffffffffu, sc, o);
            if (lane >= o) sc += v;
        }
        float p = sc - L;
        float o0 = a0 - p; p += a0;
        float o1 = a1 - p; p += a1;
        float o2 = a2 - p; p += a2;
        float o3 = a3 - p;
        sm[(4 * lane + 0) * 33 + h] = o0;
        sm[(4 * lane + 1) * 33 + h] = o1;
        sm[(4 * lane + 2) * 33 + h] = o2;
        sm[(4 * lane + 3) * 33 + h] = o3;
    }
    __syncthreads();

    float* obase = out + (b * TE_) * H_ + hg * 32;
#pragma unroll
    for (int k = 0; k < 16; k++) {
        int idx = tid + k * 256;
        int t = idx >> 5, hl = idx & 31;
        obase[t * H_ + hl] = sm[t * 33 + hl];
    }
}

// ---------------------------------------------------------------------------
// K1:
//   z=0 -> g_was = scan(enc @ Wa)   (scan fused in epilogue)
//   z=1 -> g_uah = dec @ Ua
//   z=2 -> g_ortho = enc - cumsum_excl(enc)
// ---------------------------------------------------------------------------
__global__ __launch_bounds__(256) void k1_kernel(const float* __restrict__ enc,
                                                 const float* __restrict__ dec,
                                                 const float* __restrict__ Wa,
                                                 const float* __restrict__ Ua) {
    __shared__ __align__(16) float sm[8320];

    if (blockIdx.z == 2) {
        int lin = blockIdx.y * 4 + blockIdx.x;
        scan_block(enc, g_ortho, lin >> 3, lin & 7, sm);
        __syncthreads();
        int lin2 = lin + 64;
        scan_block(enc, g_ortho, lin2 >> 3, lin2 & 7, sm);
        return;
    }

    const int z = blockIdx.z;
    const float* A = z ? dec : enc;
    const float* W = z ? Ua  : Wa;
    float*       C = z ? g_uah : g_was;

    float (*As)[132] = (float (*)[132])sm;
    float (*Bs)[68]  = (float (*)[68])(sm + 4224);

    const int bm = blockIdx.y * BM;
    const int bn = blockIdx.x * BN;
    const int tid = threadIdx.x;
    const int warp = tid >> 5;
    const int lane = tid & 31;
    const int tr = tid >> 4;
    const int tc = tid & 15;

    const int r0 = tid >> 2;
    const int qa = tid & 3;
    const int lbk = tid >> 4;
    const int lbq = tid & 15;

    float acc[8][4];
#pragma unroll
    for (int i = 0; i < 8; i++)
#pragma unroll
        for (int j = 0; j < 4; j++) acc[i][j] = 0.0f;

    float4 pa0 = *(const float4*)&A[(bm + r0) * 256 + qa * 4];
    float4 pa1 = *(const float4*)&A[(bm + r0 + 64) * 256 + qa * 4];
    float4 pb  = *(const float4*)&W[lbk * 256 + bn + lbq * 4];

    As[qa * 4 + 0][r0] = pa0.x;  As[qa * 4 + 1][r0] = pa0.y;
    As[qa * 4 + 2][r0] = pa0.z;  As[qa * 4 + 3][r0] = pa0.w;
    As[qa * 4 + 0][r0 + 64] = pa1.x;  As[qa * 4 + 1][r0 + 64] = pa1.y;
    As[qa * 4 + 2][r0 + 64] = pa1.z;  As[qa * 4 + 3][r0 + 64] = pa1.w;
    *(float4*)&Bs[lbk][lbq * 4] = pb;
    __syncthreads();

#pragma unroll 1
    for (int kt = 0; kt < 16; kt++) {
        if (kt < 15) {
            int k0 = (kt + 1) * BK;
            pa0 = *(const float4*)&A[(bm + r0) * 256 + k0 + qa * 4];
            pa1 = *(const float4*)&A[(bm + r0 + 64) * 256 + k0 + qa * 4];
            pb  = *(const float4*)&W[(k0 + lbk) * 256 + bn + lbq * 4];
        }
        const int cb = (kt & 1) * 16;
#pragma unroll
        for (int kk = 0; kk < 16; kk++) {
            float4 aLo = *(const float4*)&As[cb + kk][tr * 8];
            float4 aHi = *(const float4*)&As[cb + kk][tr * 8 + 4];
            float4 b4  = *(const float4*)&Bs[cb + kk][tc * 4];
            float am[8] = {aLo.x, aLo.y, aLo.z, aLo.w, aHi.x, aHi.y, aHi.z, aHi.w};
#pragma unroll
            for (int i = 0; i < 8; i++) {
                acc[i][0] = fmaf(am[i], b4.x, acc[i][0]);
                acc[i][1] = fmaf(am[i], b4.y, acc[i][1]);
                acc[i][2] = fmaf(am[i], b4.z, acc[i][2]);
                acc[i][3] = fmaf(am[i], b4.w, acc[i][3]);
            }
        }
        if (kt < 15) {
            const int nb = ((kt + 1) & 1) * 16;
            As[nb + qa * 4 + 0][r0] = pa0.x;  As[nb + qa * 4 + 1][r0] = pa0.y;
            As[nb + qa * 4 + 2][r0] = pa0.z;  As[nb + qa * 4 + 3][r0] = pa0.w;
            As[nb + qa * 4 + 0][r0 + 64] = pa1.x;  As[nb + qa * 4 + 1][r0 + 64] = pa1.y;
            As[nb + qa * 4 + 2][r0 + 64] = pa1.z;  As[nb + qa * 4 + 3][r0 + 64] = pa1.w;
            *(float4*)&Bs[nb + lbk][lbq * 4] = pb;
            __syncthreads();
        }
    }

    if (z == 1) {
#pragma unroll
        for (int i = 0; i < 8; i++) {
            float4 o;
            o.x = acc[i][0]; o.y = acc[i][1]; o.z = acc[i][2]; o.w = acc[i][3];
            *(float4*)&C[(bm + tr * 8 + i) * 256 + bn + tc * 4] = o;
        }
        return;
    }

    // z == 0: fused scan epilogue
    __syncthreads();
    float* sb = sm;
#pragma unroll
    for (int i = 0; i < 8; i++) {
        int t = tr * 8 + i;
#pragma unroll
        for (int j = 0; j < 4; j++)
            sb[t * 65 + tc * 4 + j] = acc[i][j];
    }
    __syncthreads();

#pragma unroll
    for (int c = 0; c < 8; c++) {
        int col = warp * 8 + c;
        float a0 = sb[(4 * lane + 0) * 65 + col];
        float a1 = sb[(4 * lane + 1) * 65 + col];
        float a2 = sb[(4 * lane + 2) * 65 + col];
        float a3 = sb[(4 * lane + 3) * 65 + col];
        float L = (a0 + a1) + (a2 + a3);
        float sc = L;
#pragma unroll
        for (int o = 1; o < 32; o <<= 1) {
            float v = __shfl_up_sync(0xffffffffu, sc, o);
            if (lane >= o) sc += v;
        }
        float p = sc - L;
        float o0 = a0 - p; p += a0;
        float o1 = a1 - p; p += a1;
        float o2 = a2 - p; p += a2;
        float o3 = a3 - p;
        sb[(4 * lane + 0) * 65 + col] = o0;
        sb[(4 * lane + 1) * 65 + col] = o1;
        sb[(4 * lane + 2) * 65 + col] = o2;
        sb[(4 * lane + 3) * 65 + col] = o3;
    }
    __syncthreads();

#pragma unroll
    for (int k = 0; k < 32; k++) {
        int idx = tid + k * 256;
        int t = idx >> 6, c = idx & 63;
        C[(bm + t) * 256 + bn + c] = sb[t * 65 + c];
    }
}

// ---------------------------------------------------------------------------
// K2: energies + softmax; tanh via f16x2 MUFU (half the MUFU ops).
// Block = (b, tile of 4 d), 512 threads = 16 warps.
// ---------------------------------------------------------------------------
__global__ __launch_bounds__(512) void energy_kernel(const float* __restrict__ Va,
                                                     float* __restrict__ e_out) {
    const int b    = blockIdx.y;
    const int d0   = blockIdx.x * 4;
    const int tid  = threadIdx.x;
    const int warp = tid >> 5;
    const int lane = tid & 31;
    const int wd   = warp & 3;
    const int eq   = warp >> 2;

    __shared__ float part[16][16][33];
    __shared__ float en_s[4][TE_];

    const int d = d0 + wd;

    const float4 v0 = *(const float4*)(Va + 4 * lane);
    const float4 v1 = *(const float4*)(Va + 128 + 4 * lane);
    const float* urow = g_uah + ((b * TD_) + d) * H_;
    const float4 u0 = *(const float4*)(urow + 4 * lane);
    const float4 u1 = *(const float4*)(urow + 128 + 4 * lane);

    const float* wbase = g_was + (b * TE_) * H_;
    const int ebase = eq * 32;

#pragma unroll
    for (int c0 = 0; c0 < 32; c0 += 16) {
#pragma unroll 4
        for (int el = 0; el < 16; el++) {
            const float* wr = wbase + (ebase + c0 + el) * H_;
            float4 w0 = *(const float4*)(wr + 4 * lane);
            float4 w1 = *(const float4*)(wr + 128 + 4 * lane);
            __half2 p0 = __floats2half2_rn(w0.x + u0.x, w0.y + u0.y);
            __half2 p1 = __floats2half2_rn(w0.z + u0.z, w0.w + u0.w);
            __half2 p2 = __floats2half2_rn(w1.x + u1.x, w1.y + u1.y);
            __half2 p3 = __floats2half2_rn(w1.z + u1.z, w1.w + u1.w);
            p0 = tanh2_fast(p0);
            p1 = tanh2_fast(p1);
            p2 = tanh2_fast(p2);
            p3 = tanh2_fast(p3);
            float2 f0 = __half22float2(p0);
            float2 f1 = __half22float2(p1);
            float2 f2 = __half22float2(p2);
            float2 f3 = __half22float2(p3);
            float s = f0.x * v0.x;
            s = fmaf(f0.y, v0.y, s);
            s = fmaf(f1.x, v0.z, s);
            s = fmaf(f1.y, v0.w, s);
            s = fmaf(f2.x, v1.x, s);
            s = fmaf(f2.y, v1.y, s);
            s = fmaf(f3.x, v1.z, s);
            s = fmaf(f3.y, v1.w, s);
            part[warp][el][lane] = s;
        }
        __syncwarp();
        if (lane < 16) {
            float s = 0.0f;
#pragma unroll
            for (int j = 0; j < 32; j++) s += part[warp][lane][j];
            en_s[wd][ebase + c0 + lane] = s;
        }
        __syncwarp();
    }
    __syncthreads();

    // Softmax over e (warps 0-3, one d each), write probs to e_out
    if (warp < 4) {
        float v0s = en_s[wd][lane];
        float v1s = en_s[wd][lane + 32];
        float v2s = en_s[wd][lane + 64];
        float v3s = en_s[wd][lane + 96];
        float m = fmaxf(fmaxf(v0s, v1s), fmaxf(v2s, v3s));
#pragma unroll
        for (int o = 16; o > 0; o >>= 1)
            m = fmaxf(m, __shfl_xor_sync(0xffffffffu, m, o));
        float e0v = __expf(v0s - m), e1v = __expf(v1s - m);
        float e2v = __expf(v2s - m), e3v = __expf(v3s - m);
        float s = e0v + e1v + e2v + e3v;
#pragma unroll
        for (int o = 16; o > 0; o >>= 1)
            s += __shfl_xor_sync(0xffffffffu, s, o);
        float inv = __fdividef(1.0f, s);
        float* eo = e_out + ((b * TD_) + d) * TE_;
        eo[lane]      = e0v * inv;
        eo[lane + 32] = e1v * inv;
        eo[lane + 64] = e2v * inv;
        eo[lane + 96] = e3v * inv;
    }
}

// ---------------------------------------------------------------------------
// K3: context batched GEMM.  c_out[b] = P[b] (TD x TE) @ g_ortho[b] (TE x H)
// ---------------------------------------------------------------------------
__global__ __launch_bounds__(256) void ctx_kernel(const float* __restrict__ P,
                                                  float* __restrict__ c_out) {
    __shared__ __align__(16) float sm[2 * 16 * 68 * 2];

    float (*As)[68] = (float (*)[68])sm;
    float (*Bs)[68] = (float (*)[68])(sm + 2 * 16 * 68);

    const int bz = blockIdx.z;
    const int bm = blockIdx.y * 64;
    const int bn = blockIdx.x * 64;
    const int tid = threadIdx.x;
    const int tr = tid >> 4;
    const int tc = tid & 15;

    const float* A = P       + bz * TD_ * TE_;
    const float* W = g_ortho + bz * TE_ * H_;
    float*       C = c_out   + bz * TD_ * H_;

    const int r0 = tid >> 2;
    const int qa = tid & 3;
    const int lbk = tid >> 4;
    const int lbq = tid & 15;

    float acc[4][4];
#pragma unroll
    for (int i = 0; i < 4; i++)
#pragma unroll
        for (int j = 0; j < 4; j++) acc[i][j] = 0.0f;

    float4 pa = *(const float4*)&A[(bm + r0) * TE_ + qa * 4];
    float4 pb = *(const float4*)&W[lbk * H_ + bn + lbq * 4];
    As[qa * 4 + 0][r0] = pa.x;  As[qa * 4 + 1][r0] = pa.y;
    As[qa * 4 + 2][r0] = pa.z;  As[qa * 4 + 3][r0] = pa.w;
    *(float4*)&Bs[lbk][lbq * 4] = pb;
    __syncthreads();

#pragma unroll 1
    for (int kt = 0; kt < 8; kt++) {
        if (kt < 7) {
            int k0 = (kt + 1) * 16;
            pa = *(const float4*)&A[(bm + r0) * TE_ + k0 + qa * 4];
            pb = *(const float4*)&W[(k0 + lbk) * H_ + bn + lbq * 4];
        }
        const int cb = (kt & 1) * 16;
#pragma unroll
        for (int kk = 0; kk < 16; kk++) {
            float4 a4 = *(const float4*)&As[cb + kk][tr * 4];
            float4 b4 = *(const float4*)&Bs[cb + kk][tc * 4];
            acc[0][0] = fmaf(a4.x, b4.x, acc[0][0]);
            acc[0][1] = fmaf(a4.x, b4.y, acc[0][1]);
            acc[0][2] = fmaf(a4.x, b4.z, acc[0][2]);
            acc[0][3] = fmaf(a4.x, b4.w, acc[0][3]);
            acc[1][0] = fmaf(a4.y, b4.x, acc[1][0]);
            acc[1][1] = fmaf(a4.y, b4.y, acc[1][1]);
            acc[1][2] = fmaf(a4.y, b4.z, acc[1][2]);
            acc[1][3] = fmaf(a4.y, b4.w, acc[1][3]);
            acc[2][0] = fmaf(a4.z, b4.x, acc[2][0]);
            acc[2][1] = fmaf(a4.z, b4.y, acc[2][1]);
            acc[2][2] = fmaf(a4.z, b4.z, acc[2][2]);
            acc[2][3] = fmaf(a4.z, b4.w, acc[2][3]);
            acc[3][0] = fmaf(a4.w, b4.x, acc[3][0]);
            acc[3][1] = fmaf(a4.w, b4.y, acc[3][1]);
            acc[3][2] = fmaf(a4.w, b4.z, acc[3][2]);
            acc[3][3] = fmaf(a4.w, b4.w, acc[3][3]);
        }
        if (kt < 7) {
            const int nb = ((kt + 1) & 1) * 16;
            As[nb + qa * 4 + 0][r0] = pa.x;  As[nb + qa * 4 + 1][r0] = pa.y;
            As[nb + qa * 4 + 2][r0] = pa.z;  As[nb + qa * 4 + 3][r0] = pa.w;
            *(float4*)&Bs[nb + lbk][lbq * 4] = pb;
            __syncthreads();
        }
    }

#pragma unroll
    for (int i = 0; i < 4; i++) {
        float4 o;
        o.x = acc[i][0]; o.y = acc[i][1]; o.z = acc[i][2]; o.w = acc[i][3];
        *(float4*)&C[(bm + tr * 4 + i) * H_ + bn + tc * 4] = o;
    }
}

// ---------------------------------------------------------------------------
extern "C" void kernel_launch(void* const* d_in, const int* in_sizes, int n_in,
                              void* d_out, int out_size) {
    const float* enc = (const float*)d_in[0];   // [16,128,256]
    const float* dec = (const float*)d_in[1];   // [16,128,256]
    const float* Wa  = (const float*)d_in[2];   // [256,256]
    const float* Ua  = (const float*)d_in[3];   // [256,256]
    const float* Va  = (const float*)d_in[4];   // [256,1]

    float* out   = (float*)d_out;
    float* c_out = out;                          // [16,128,256]
    float* e_out = out + B_ * TD_ * H_;          // [16,128,128]

    k1_kernel<<<dim3(4, 16, 3), 256>>>(enc, dec, Wa, Ua);
    energy_kernel<<<dim3(TD_ / 4, B_), 512>>>(Va, e_out);
    ctx_kernel<<<dim3(4, 2, 16), 256>>>(e_out, c_out);
}